// round 1
// baseline (speedup 1.0000x reference)
#include <cuda_runtime.h>

// PolicyEncoder gather-sum:
// out[n, :] = bias + w_state0[obs0[n]] + w_state1[obs1[n]] + w_act0[act0[n]] + w_act1[act1[n]]
// N = 262144 rows, D = 128 floats per row.
//
// Layout: one warp per output row. Each lane owns one float4 (4 floats),
// 32 lanes * 4 = 128 floats = one row. Every gathered row read is a single
// coalesced 512B transaction; output is a perfectly coalesced stream.

__global__ void __launch_bounds__(256)
policy_encoder_kernel(const int* __restrict__ obs0,
                      const int* __restrict__ obs1,
                      const int* __restrict__ act0,
                      const int* __restrict__ act1,
                      const float4* __restrict__ w0,   // [OBS0, 32] as float4
                      const float4* __restrict__ w1,   // [OBS1, 32]
                      const float4* __restrict__ w2,   // [ACT0, 32]
                      const float4* __restrict__ w3,   // [ACT1, 32]
                      const float4* __restrict__ bias, // [32]
                      float4* __restrict__ out,        // [N, 32]
                      int n)
{
    const int gtid = blockIdx.x * blockDim.x + threadIdx.x;
    const int row  = gtid >> 5;        // warp index = output row
    const int lane = gtid & 31;        // float4 slot within the row
    if (row >= n) return;

    // All lanes load the same index word -> one sector per array, broadcast.
    const int i0 = __ldg(obs0 + row);
    const int i1 = __ldg(obs1 + row);
    const int i2 = __ldg(act0 + row);
    const int i3 = __ldg(act1 + row);

    const float4 b  = __ldg(bias + lane);
    const float4 v0 = __ldg(w0 + (size_t)i0 * 32 + lane);
    const float4 v1 = __ldg(w1 + (size_t)i1 * 32 + lane);
    const float4 v2 = __ldg(w2 + (size_t)i2 * 32 + lane);
    const float4 v3 = __ldg(w3 + (size_t)i3 * 32 + lane);

    float4 r;
    r.x = b.x + v0.x + v1.x + v2.x + v3.x;
    r.y = b.y + v0.y + v1.y + v2.y + v3.y;
    r.z = b.z + v0.z + v1.z + v2.z + v3.z;
    r.w = b.w + v0.w + v1.w + v2.w + v3.w;

    out[(size_t)row * 32 + lane] = r;
}

extern "C" void kernel_launch(void* const* d_in, const int* in_sizes, int n_in,
                              void* d_out, int out_size)
{
    const int*    obs0 = (const int*)d_in[0];
    const int*    obs1 = (const int*)d_in[1];
    const int*    act0 = (const int*)d_in[2];
    const int*    act1 = (const int*)d_in[3];
    const float4* w0   = (const float4*)d_in[4];
    const float4* w1   = (const float4*)d_in[5];
    const float4* w2   = (const float4*)d_in[6];
    const float4* w3   = (const float4*)d_in[7];
    const float4* bias = (const float4*)d_in[8];
    float4*       out  = (float4*)d_out;

    const int n = in_sizes[0];                 // number of rows (N)
    const int threads = 256;                   // 8 warps = 8 rows per block
    const int rows_per_block = threads / 32;
    const int blocks = (n + rows_per_block - 1) / rows_per_block;

    policy_encoder_kernel<<<blocks, threads>>>(obs0, obs1, act0, act1,
                                               w0, w1, w2, w3, bias, out, n);
}

// round 2
// speedup vs baseline: 1.0752x; 1.0752x over previous
#include <cuda_runtime.h>

// PolicyEncoder gather-sum:
// out[n, :] = bias + w_state0[obs0[n]] + w_state1[obs1[n]] + w_act0[act0[n]] + w_act1[act1[n]]
// N = 262144 rows, D = 128 floats per row.
//
// R2 changes vs R1:
//  - Output stored with __stcs (evict-first streaming hint). Output is
//    write-once; keeping it out of L2 lets the 78MB of embedding tables stay
//    L2-resident across graph replays -> table gathers become L2 hits.
//  - 2 rows per warp: 8 independent 512B gathers in flight per warp for
//    better memory-level parallelism; index/addressing cost amortized.

__global__ void __launch_bounds__(256)
policy_encoder_kernel(const int* __restrict__ obs0,
                      const int* __restrict__ obs1,
                      const int* __restrict__ act0,
                      const int* __restrict__ act1,
                      const float4* __restrict__ w0,   // [OBS0, 32] as float4
                      const float4* __restrict__ w1,   // [OBS1, 32]
                      const float4* __restrict__ w2,   // [ACT0, 32]
                      const float4* __restrict__ w3,   // [ACT1, 32]
                      const float4* __restrict__ bias, // [32]
                      float4* __restrict__ out,        // [N, 32]
                      int n)
{
    const int gtid = blockIdx.x * blockDim.x + threadIdx.x;
    const int warp = gtid >> 5;
    const int lane = gtid & 31;

    const int row0 = warp * 2;          // this warp handles rows row0, row0+1
    if (row0 >= n) return;
    const bool has2 = (row0 + 1) < n;

    const float4 b = __ldg(bias + lane);

    // Row 0 indices (broadcast loads: one sector per array per warp)
    const int a0 = __ldg(obs0 + row0);
    const int a1 = __ldg(obs1 + row0);
    const int a2 = __ldg(act0 + row0);
    const int a3 = __ldg(act1 + row0);
    // Row 1 indices
    const int c0 = has2 ? __ldg(obs0 + row0 + 1) : 0;
    const int c1 = has2 ? __ldg(obs1 + row0 + 1) : 0;
    const int c2 = has2 ? __ldg(act0 + row0 + 1) : 0;
    const int c3 = has2 ? __ldg(act1 + row0 + 1) : 0;

    // Issue all 8 gathers back-to-back for maximum MLP.
    const float4 u0 = __ldg(w0 + (size_t)a0 * 32 + lane);
    const float4 u1 = __ldg(w1 + (size_t)a1 * 32 + lane);
    const float4 u2 = __ldg(w2 + (size_t)a2 * 32 + lane);
    const float4 u3 = __ldg(w3 + (size_t)a3 * 32 + lane);
    const float4 v0 = __ldg(w0 + (size_t)c0 * 32 + lane);
    const float4 v1 = __ldg(w1 + (size_t)c1 * 32 + lane);
    const float4 v2 = __ldg(w2 + (size_t)c2 * 32 + lane);
    const float4 v3 = __ldg(w3 + (size_t)c3 * 32 + lane);

    float4 r0;
    r0.x = b.x + u0.x + u1.x + u2.x + u3.x;
    r0.y = b.y + u0.y + u1.y + u2.y + u3.y;
    r0.z = b.z + u0.z + u1.z + u2.z + u3.z;
    r0.w = b.w + u0.w + u1.w + u2.w + u3.w;

    __stcs(out + (size_t)row0 * 32 + lane, r0);   // evict-first: keep L2 for tables

    if (has2) {
        float4 r1;
        r1.x = b.x + v0.x + v1.x + v2.x + v3.x;
        r1.y = b.y + v0.y + v1.y + v2.y + v3.y;
        r1.z = b.z + v0.z + v1.z + v2.z + v3.z;
        r1.w = b.w + v0.w + v1.w + v2.w + v3.w;
        __stcs(out + (size_t)(row0 + 1) * 32 + lane, r1);
    }
}

extern "C" void kernel_launch(void* const* d_in, const int* in_sizes, int n_in,
                              void* d_out, int out_size)
{
    const int*    obs0 = (const int*)d_in[0];
    const int*    obs1 = (const int*)d_in[1];
    const int*    act0 = (const int*)d_in[2];
    const int*    act1 = (const int*)d_in[3];
    const float4* w0   = (const float4*)d_in[4];
    const float4* w1   = (const float4*)d_in[5];
    const float4* w2   = (const float4*)d_in[6];
    const float4* w3   = (const float4*)d_in[7];
    const float4* bias = (const float4*)d_in[8];
    float4*       out  = (float4*)d_out;

    const int n = in_sizes[0];                 // number of rows (N)
    const int threads = 256;                   // 8 warps/block, 2 rows/warp
    const int rows_per_block = (threads / 32) * 2;
    const int blocks = (n + rows_per_block - 1) / rows_per_block;

    policy_encoder_kernel<<<blocks, threads>>>(obs0, obs1, act0, act1,
                                               w0, w1, w2, w3, bias, out, n);
}